// round 7
// baseline (speedup 1.0000x reference)
#include <cuda_runtime.h>
#include <cuda_fp16.h>
#include <math.h>
#include <stdint.h>

#define H     1024
#define BATCH 256
#define NCAM  15
#define NT    60
#define G3H   3072

#define TM 64
#define TJ 32
#define TN 96
#define KC 64
#define NK (H/KC)
#define NSA 2                 // A ring stages
#define NSB 3                 // B ring stages
#define A_STG 8192
#define B_STG 12288
#define SMEM_MAIN (NSA*A_STG + NSB*B_STG)   // 53248
#define SMEM_DYN  (SMEM_MAIN + 64)

// ---------------- scratch (static device globals) ----------------
__device__ __align__(128) char g_Pwih[(size_t)NCAM*32*NK*B_STG];
__device__ __align__(128) char g_Pwhh[(size_t)NCAM*32*NK*B_STG];
// A packs: [c][kt][8KB], 64 camera-sorted rows, zero-padded, pre-swizzled
__device__ __align__(128) char g_xpack[(size_t)NCAM*NK*A_STG];
__device__ __align__(128) char g_hPA [(size_t)NCAM*NK*A_STG];
__device__ __align__(128) char g_hPB [(size_t)NCAM*NK*A_STG];
__device__ __align__(128) float g_hA[BATCH*H];
__device__ __align__(128) float g_hB[BATCH*H];
__device__ __align__(128) float g_gi[(size_t)BATCH*G3H];   // gi + b_ih + b_hh(r,z)
__device__ __align__(128) float g_hs[(size_t)NT*BATCH*H];
__device__ int g_order[BATCH];
__device__ int g_seg[NCAM+1];

// ---------------- ptx helpers ----------------
__device__ __forceinline__ void mbar_init(uint32_t a, uint32_t cnt){
    asm volatile("mbarrier.init.shared.b64 [%0], %1;" :: "r"(a), "r"(cnt) : "memory");
}
__device__ __forceinline__ void mbar_expect(uint32_t a, uint32_t tx){
    asm volatile("mbarrier.arrive.expect_tx.shared.b64 _, [%0], %1;" :: "r"(a), "r"(tx) : "memory");
}
__device__ __forceinline__ void bulk_g2s(uint32_t dst, const void* src, uint32_t bytes, uint32_t mbar){
    asm volatile("cp.async.bulk.shared::cta.global.mbarrier::complete_tx::bytes [%0], [%1], %2, [%3];"
                 :: "r"(dst), "l"(src), "r"(bytes), "r"(mbar) : "memory");
}
__device__ __forceinline__ void mbar_wait(uint32_t a, uint32_t phase){
    asm volatile("{\n\t.reg .pred P;\n\t"
                 "WL_%=:\n\t"
                 "mbarrier.try_wait.parity.acquire.cta.shared::cta.b64 P, [%0], %1, 0x989680;\n\t"
                 "@P bra.uni WD_%=;\n\t"
                 "bra.uni WL_%=;\n\t"
                 "WD_%=:\n\t}"
                 :: "r"(a), "r"(phase) : "memory");
}
__device__ __forceinline__ float sigf(float x){ return 1.f/(1.f + __expf(-x)); }
__device__ __forceinline__ float tanhfast(float x){ return 2.f/(1.f + __expf(-2.f*x)) - 1.f; }

// ---------------- setup: group samples by camera ----------------
__global__ void setup_kernel(const int* __restrict__ cam){
    __shared__ int cnt[NCAM], offs[NCAM];
    int tid = threadIdx.x;
    if (tid < NCAM) cnt[tid] = 0;
    __syncthreads();
    int c = cam[tid];
    atomicAdd(&cnt[c], 1);
    __syncthreads();
    if (tid == 0){
        int s = 0;
        for (int i = 0; i < NCAM; i++){ offs[i] = s; g_seg[i] = s; s += cnt[i]; }
        g_seg[NCAM] = s;
    }
    __syncthreads();
    int p = atomicAdd(&offs[c], 1);
    g_order[p] = tid;
}

// ---------------- init: pack x (sorted+swizzled, 64 rows/cam), zero hP/hA ----------------
#define XCH (NCAM*NK*512)     // 16B chunks of an A-pack buffer
__global__ void init_pack_kernel(const float* __restrict__ x){
    const int total = 3*XCH + BATCH*H/4;
    int stride = gridDim.x*blockDim.x;
    for (int i = blockIdx.x*blockDim.x + threadIdx.x; i < total; i += stride){
        if (i < XCH){
            int blk = i >> 9, cin = i & 511;
            int r = cin >> 3, ch = cin & 7;      // r 0..63
            int kt = blk & 15, c = blk >> 4;
            int seg0 = g_seg[c], bc = g_seg[c+1]-seg0;
            uint4 v = make_uint4(0,0,0,0);
            if (r < bc){
                int bidx = g_order[seg0+r];
                const float4* s = (const float4*)(x + (size_t)bidx*H + kt*KC + ch*8);
                float4 a = s[0], b = s[1];
                __half2 h0 = __floats2half2_rn(a.x,a.y), h1 = __floats2half2_rn(a.z,a.w);
                __half2 h2 = __floats2half2_rn(b.x,b.y), h3 = __floats2half2_rn(b.z,b.w);
                v.x = *(uint32_t*)&h0; v.y = *(uint32_t*)&h1;
                v.z = *(uint32_t*)&h2; v.w = *(uint32_t*)&h3;
            }
            *(uint4*)(g_xpack + (size_t)blk*A_STG + r*128 + ((ch ^ (r&7))<<4)) = v;
        } else if (i < 3*XCH){
            int k = i - XCH;
            if (k < XCH) ((uint4*)g_hPA)[k] = make_uint4(0,0,0,0);
            else         ((uint4*)g_hPB)[k-XCH] = make_uint4(0,0,0,0);
        } else {
            int k = i - 3*XCH;
            ((float4*)g_hA)[k] = make_float4(0.f,0.f,0.f,0.f);
        }
    }
}

// ---------------- convert + pack weights fp32 -> fp16 swizzled tiles ----------------
__global__ void convert_pack_kernel(const float* __restrict__ wi, const float* __restrict__ wh){
    const size_t NCH = (size_t)NCAM*32*NK*768;
    size_t stride = (size_t)gridDim.x*blockDim.x;
    for (size_t i = (size_t)blockIdx.x*blockDim.x + threadIdx.x; i < NCH; i += stride){
        size_t blk = i / 768; int cin = (int)(i % 768);
        int r = cin >> 3, ch = cin & 7;
        int kt = (int)(blk & 15); size_t cj = blk >> 4;
        int jt = (int)(cj & 31); int c = (int)(cj >> 5);
        int grow = ((r>>5)<<10) + jt*TJ + (r & 31);
        size_t src = (((size_t)c*G3H + grow)<<10) + kt*KC + ch*8;
        size_t dst = blk*B_STG + r*128 + ((ch ^ (r&7))<<4);
        {
            const float4* s = (const float4*)(wi + src);
            float4 a = __ldcs(s), b = __ldcs(s+1);
            __half2 h0 = __floats2half2_rn(a.x,a.y), h1 = __floats2half2_rn(a.z,a.w);
            __half2 h2 = __floats2half2_rn(b.x,b.y), h3 = __floats2half2_rn(b.z,b.w);
            uint4 v; v.x=*(uint32_t*)&h0; v.y=*(uint32_t*)&h1; v.z=*(uint32_t*)&h2; v.w=*(uint32_t*)&h3;
            __stcs((uint4*)(g_Pwih + dst), v);
        }
        {
            const float4* s = (const float4*)(wh + src);
            float4 a = __ldcs(s), b = __ldcs(s+1);
            __half2 h0 = __floats2half2_rn(a.x,a.y), h1 = __floats2half2_rn(a.z,a.w);
            __half2 h2 = __floats2half2_rn(b.x,b.y), h3 = __floats2half2_rn(b.z,b.w);
            uint4 v; v.x=*(uint32_t*)&h0; v.y=*(uint32_t*)&h1; v.z=*(uint32_t*)&h2; v.w=*(uint32_t*)&h3;
            *(uint4*)(g_Pwhh + dst) = v;
        }
    }
}

// ---------------- bulk-fed GEMM (TM=64) + fused GRU epilogue ----------------
template<int MODE>
__global__ void __launch_bounds__(256, 4) gemm_step_kernel(const float* __restrict__ b_ih,
                                                           const float* __restrict__ b_hh,
                                                           int t)
{
    extern __shared__ __align__(128) char smem[];
    const int jt = blockIdx.x;
    const int c  = blockIdx.y;
    const int seg0 = g_seg[c];
    const int bc   = g_seg[c+1] - seg0;
    if (bc == 0) return;

    const char* __restrict__ Apack = (MODE==0) ? g_xpack : ((t & 1) ? g_hPB : g_hPA);
    const char* __restrict__ Bpack = (MODE==0) ? g_Pwih : g_Pwhh;
    const char* Asrc = Apack + (size_t)(c*NK)*A_STG;
    const char* Bsrc = Bpack + (size_t)((c*32+jt)*NK)*B_STG;

    const int j0   = jt*TJ;
    const int tid  = threadIdx.x;
    const int lane = tid & 31, warp = tid >> 5;
    const int wm = warp & 3, wn = warp >> 2;   // 4(m) x 2(n=48)
    uint32_t smem_u32 = (uint32_t)__cvta_generic_to_shared(smem);
    uint32_t mbA = smem_u32 + SMEM_MAIN;       // 2 barriers
    uint32_t mbB = mbA + 16;                   // 3 barriers

    if (tid == 0){
        mbar_init(mbA + 0, 1); mbar_init(mbA + 8, 1);
        #pragma unroll
        for (int s = 0; s < NSB; s++) mbar_init(mbB + s*8, 1);
        asm volatile("fence.proxy.async.shared::cta;" ::: "memory");
    }
    __syncthreads();

    auto issueA = [&](int kt){
        if (kt < NK){
            int s = kt & 1;
            mbar_expect(mbA + s*8, A_STG);
            bulk_g2s(smem_u32 + s*A_STG, Asrc + (size_t)kt*A_STG, A_STG, mbA + s*8);
        }
    };
    auto issueB = [&](int kt){
        if (kt < NK){
            int s = kt % NSB;
            mbar_expect(mbB + s*8, B_STG);
            bulk_g2s(smem_u32 + NSA*A_STG + s*B_STG, Bsrc + (size_t)kt*B_STG, B_STG, mbB + s*8);
        }
    };
    if (tid == 0){ issueA(0); issueA(1); issueB(0); issueB(1); issueB(2); }

    float acc[6][4];
    #pragma unroll
    for (int i = 0; i < 6; i++)
        #pragma unroll
        for (int j = 0; j < 4; j++) acc[i][j] = 0.f;

    const int rowA = wm*16 + (lane & 7) + (lane & 8);
    const int cbA  = lane >> 4;
    const int rowBl = lane & 7;
    const int cbB  = (lane >> 3) & 1;

    for (int kt = 0; kt < NK; kt++){
        int sa = kt & 1, sb = kt % NSB;
        mbar_wait(mbA + sa*8, (kt >> 1) & 1);
        mbar_wait(mbB + sb*8, (kt/NSB) & 1);
        uint32_t sA = smem_u32 + sa*A_STG;
        uint32_t sB = smem_u32 + NSA*A_STG + sb*B_STG;
        #pragma unroll
        for (int k16 = 0; k16 < KC/16; k16++){
            int cb = k16*2;
            uint32_t aaddr = sA + rowA*128 + (((cb + cbA) ^ (rowA & 7)) << 4);
            uint32_t a0,a1,a2,a3;
            asm volatile("ldmatrix.sync.aligned.m8n8.x4.shared.b16 {%0,%1,%2,%3}, [%4];"
                         : "=r"(a0),"=r"(a1),"=r"(a2),"=r"(a3) : "r"(aaddr));
            #pragma unroll
            for (int nt = 0; nt < 6; nt++){
                int rB = wn*48 + nt*8 + rowBl;
                uint32_t baddr = sB + rB*128 + (((cb + cbB) ^ (rB & 7)) << 4);
                uint32_t b0,b1;
                asm volatile("ldmatrix.sync.aligned.m8n8.x2.shared.b16 {%0,%1}, [%2];"
                             : "=r"(b0),"=r"(b1) : "r"(baddr));
                asm volatile("mma.sync.aligned.m16n8k16.row.col.f32.f16.f16.f32 "
                             "{%0,%1,%2,%3}, {%4,%5,%6,%7}, {%8,%9}, {%0,%1,%2,%3};"
                             : "+f"(acc[nt][0]),"+f"(acc[nt][1]),"+f"(acc[nt][2]),"+f"(acc[nt][3])
                             : "r"(a0),"r"(a1),"r"(a2),"r"(a3),"r"(b0),"r"(b1));
            }
        }
        __syncthreads();
        if (tid == 0){ issueA(kt + NSA); issueB(kt + NSB); }
    }

    // stash gh tile 64 x 96 (stride 104 floats), fused epilogue
    float* ghs = (float*)smem;
    {
        int r0 = wm*16 + (lane >> 2);
        int colb = (lane & 3)*2;
        #pragma unroll
        for (int nt = 0; nt < 6; nt++){
            int ccol = wn*48 + nt*8 + colb;
            ghs[r0*104 + ccol]         = acc[nt][0];
            ghs[r0*104 + ccol + 1]     = acc[nt][1];
            ghs[(r0+8)*104 + ccol]     = acc[nt][2];
            ghs[(r0+8)*104 + ccol + 1] = acc[nt][3];
        }
    }
    __syncthreads();

    if (MODE == 0){
        #pragma unroll
        for (int l = 0; l < 6; l++){
            int idx = tid + l*256;          // 1536 float4 total
            int m = idx / 24, q = idx % 24;
            int nl = q*4;
            if (m < bc){
                int bidx = g_order[seg0 + m];
                int g = nl >> 5, jj = nl & 31;
                int wrow = (g<<10) + j0 + jj;
                float4 v = *(float4*)&ghs[m*104 + nl];
                float4 bi = __ldg((const float4*)(b_ih + (size_t)c*G3H + wrow));
                v.x += bi.x; v.y += bi.y; v.z += bi.z; v.w += bi.w;
                if (g < 2){
                    float4 bh = __ldg((const float4*)(b_hh + (size_t)c*G3H + wrow));
                    v.x += bh.x; v.y += bh.y; v.z += bh.z; v.w += bh.w;
                }
                *(float4*)(g_gi + (size_t)bidx*G3H + wrow) = v;
            }
        }
    } else {
        const float* __restrict__ hc = (t & 1) ? g_hB : g_hA;
        float*       __restrict__ hn = (t & 1) ? g_hA : g_hB;
        char*        __restrict__ hPn = (t & 1) ? g_hPA : g_hPB;
        #pragma unroll
        for (int half = 0; half < 2; half++){
            int m = (tid >> 3) + half*32;
            int jj = (tid & 7)*4;
            if (m < bc){
                int bidx = g_order[seg0 + m];
                int j = j0 + jj;
                float4 ghr = *(float4*)&ghs[m*104 + jj];
                float4 ghz = *(float4*)&ghs[m*104 + 32 + jj];
                float4 ghn4 = *(float4*)&ghs[m*104 + 64 + jj];
                const float* gi = g_gi + (size_t)bidx*G3H;
                float4 gir = *(const float4*)(gi + j);
                float4 giz = *(const float4*)(gi + H + j);
                float4 gin = *(const float4*)(gi + 2*H + j);
                float4 bn  = __ldg((const float4*)(b_hh + (size_t)c*G3H + 2*H + j));
                float4 hold = *(const float4*)(hc + (size_t)bidx*H + j);
                float4 hv;
                {
                    float r0 = sigf(gir.x + ghr.x), z0 = sigf(giz.x + ghz.x);
                    float n0 = tanhfast(gin.x + r0*(ghn4.x + bn.x));
                    hv.x = (1.f - z0)*n0 + z0*hold.x;
                    float r1 = sigf(gir.y + ghr.y), z1 = sigf(giz.y + ghz.y);
                    float n1 = tanhfast(gin.y + r1*(ghn4.y + bn.y));
                    hv.y = (1.f - z1)*n1 + z1*hold.y;
                    float r2 = sigf(gir.z + ghr.z), z2 = sigf(giz.z + ghz.z);
                    float n2 = tanhfast(gin.z + r2*(ghn4.z + bn.z));
                    hv.z = (1.f - z2)*n2 + z2*hold.z;
                    float r3 = sigf(gir.w + ghr.w), z3 = sigf(giz.w + ghz.w);
                    float n3 = tanhfast(gin.w + r3*(ghn4.w + bn.w));
                    hv.w = (1.f - z3)*n3 + z3*hold.w;
                }
                *(float4*)(hn + (size_t)bidx*H + j) = hv;
                __stcs((float4*)(g_hs + ((size_t)t*BATCH + bidx)*H + j), hv);
                int kt = j >> 6, ch = (j >> 3) & 7, win = (j & 7)*2;
                __half2 p0 = __floats2half2_rn(hv.x, hv.y);
                __half2 p1 = __floats2half2_rn(hv.z, hv.w);
                uint2 pk; pk.x = *(uint32_t*)&p0; pk.y = *(uint32_t*)&p1;
                *(uint2*)(hPn + (size_t)(c*NK + kt)*A_STG + m*128 + ((ch ^ (m&7))<<4) + win) = pk;
            }
        }
    }
}

// ---------------- final transpose [T,B,H] -> [B,H,T] ----------------
__global__ void transpose_kernel(float* __restrict__ out){
    __shared__ float tile[NT*65];
    int b = blockIdx.y, j0 = blockIdx.x*64, tid = threadIdx.x;
    for (int idx = tid; idx < NT*64; idx += 256){
        int t = idx >> 6, jj = idx & 63;
        tile[t*65 + jj] = __ldcs(&g_hs[((size_t)t*BATCH + b)*H + j0 + jj]);
    }
    __syncthreads();
    for (int idx = tid; idx < NT*64; idx += 256){
        int jj = idx / NT, t = idx % NT;
        __stcs(&out[((size_t)b*H + j0 + jj)*NT + t], tile[t*65 + jj]);
    }
}

// ---------------- launch ----------------
extern "C" void kernel_launch(void* const* d_in, const int* in_sizes, int n_in,
                              void* d_out, int out_size)
{
    const float* x   = (const float*)d_in[0];
    const int*   cam = (const int*)  d_in[1];
    const float* Wih = (const float*)d_in[2];
    const float* Whh = (const float*)d_in[3];
    const float* bih = (const float*)d_in[4];
    const float* bhh = (const float*)d_in[5];
    float* out = (float*)d_out;

    cudaFuncSetAttribute(gemm_step_kernel<0>, cudaFuncAttributeMaxDynamicSharedMemorySize, SMEM_DYN);
    cudaFuncSetAttribute(gemm_step_kernel<1>, cudaFuncAttributeMaxDynamicSharedMemorySize, SMEM_DYN);

    setup_kernel<<<1, 256>>>(cam);
    init_pack_kernel<<<512, 256>>>(x);
    convert_pack_kernel<<<4096, 256>>>(Wih, Whh);

    dim3 grid(32, NCAM);
    gemm_step_kernel<0><<<grid, 256, SMEM_DYN>>>(bih, bhh, -1);
    for (int t = 0; t < NT; t++)
        gemm_step_kernel<1><<<grid, 256, SMEM_DYN>>>(bih, bhh, t);

    transpose_kernel<<<dim3(16, BATCH), 256>>>(out);
}

// round 8
// speedup vs baseline: 1.3436x; 1.3436x over previous
#include <cuda_runtime.h>
#include <cuda_fp16.h>
#include <math.h>
#include <stdint.h>

#define H     1024
#define BATCH 256
#define NCAM  15
#define NT    60
#define G3H   3072

#define TM 32
#define TJ 32
#define TN 96
#define KC 64
#define NK (H/KC)
#define NSTG 3
#define A_STG 4096
#define B_STG 12288
#define B_HALF 6144
#define STAGE_BYTES (A_STG + B_STG)       // 16KB
#define SMEM_MAIN (NSTG*STAGE_BYTES)
#define SMEM_DYN  (SMEM_MAIN + 64)        // + full[3] empty[3] barriers
#define MAXMT 24                          // even (cluster pairs); packed (cam,mtile)

// ---------------- scratch (static device globals) ----------------
__device__ __align__(128) char g_Pwih[(size_t)NCAM*32*NK*B_STG];
__device__ __align__(128) char g_Pwhh[(size_t)NCAM*32*NK*B_STG];
__device__ __align__(128) char g_xpack[(size_t)NCAM*2*NK*A_STG];
__device__ __align__(128) char g_hPA [(size_t)NCAM*2*NK*A_STG];
__device__ __align__(128) char g_hPB [(size_t)NCAM*2*NK*A_STG];
__device__ __align__(128) float g_hA[BATCH*H];
__device__ __align__(128) float g_hB[BATCH*H];
__device__ __align__(128) float g_gi[(size_t)BATCH*G3H];   // gi + b_ih + b_hh(r,z)
__device__ __align__(128) float g_hs[(size_t)NT*BATCH*H];
__device__ int g_order[BATCH];
__device__ int g_seg[NCAM+1];
__device__ int g_mtile[MAXMT];    // packed (c<<1)|mt; pairs-first ordering
__device__ int g_nmt;

// ---------------- ptx helpers ----------------
__device__ __forceinline__ void mbar_init(uint32_t a, uint32_t cnt){
    asm volatile("mbarrier.init.shared.b64 [%0], %1;" :: "r"(a), "r"(cnt) : "memory");
}
__device__ __forceinline__ void mbar_expect(uint32_t a, uint32_t tx){
    asm volatile("mbarrier.arrive.expect_tx.shared.b64 _, [%0], %1;" :: "r"(a), "r"(tx) : "memory");
}
__device__ __forceinline__ void mbar_arrive(uint32_t a){
    asm volatile("mbarrier.arrive.shared.b64 _, [%0];" :: "r"(a) : "memory");
}
__device__ __forceinline__ void mbar_arrive_peer(uint32_t a, uint32_t rank){
    asm volatile("{\n\t.reg .b32 ra;\n\t"
                 "mapa.shared::cluster.u32 ra, %0, %1;\n\t"
                 "mbarrier.arrive.shared::cluster.b64 _, [ra];\n\t}"
                 :: "r"(a), "r"(rank) : "memory");
}
__device__ __forceinline__ void bulk_g2s(uint32_t dst, const void* src, uint32_t bytes, uint32_t mbar){
    asm volatile("cp.async.bulk.shared::cta.global.mbarrier::complete_tx::bytes [%0], [%1], %2, [%3];"
                 :: "r"(dst), "l"(src), "r"(bytes), "r"(mbar) : "memory");
}
__device__ __forceinline__ void bulk_g2s_mc(uint32_t dst, const void* src, uint32_t bytes,
                                            uint32_t mbar, uint16_t mask){
    asm volatile("cp.async.bulk.shared::cluster.global.mbarrier::complete_tx::bytes.multicast::cluster "
                 "[%0], [%1], %2, [%3], %4;"
                 :: "r"(dst), "l"(src), "r"(bytes), "r"(mbar), "h"(mask) : "memory");
}
__device__ __forceinline__ void mbar_wait(uint32_t a, uint32_t phase){
    asm volatile("{\n\t.reg .pred P;\n\t"
                 "WL_%=:\n\t"
                 "mbarrier.try_wait.parity.acquire.cta.shared::cta.b64 P, [%0], %1, 0x989680;\n\t"
                 "@P bra.uni WD_%=;\n\t"
                 "bra.uni WL_%=;\n\t"
                 "WD_%=:\n\t}"
                 :: "r"(a), "r"(phase) : "memory");
}
#define CLUSTER_SYNC() do { \
    asm volatile("barrier.cluster.arrive.aligned;" ::: "memory"); \
    asm volatile("barrier.cluster.wait.aligned;" ::: "memory"); \
} while(0)
__device__ __forceinline__ float sigf(float x){ return 1.f/(1.f + __expf(-x)); }
__device__ __forceinline__ float tanhfast(float x){ return 2.f/(1.f + __expf(-2.f*x)) - 1.f; }

// ---------------- setup: group by camera + pairs-first mtile table ----------------
__global__ void setup_kernel(const int* __restrict__ cam){
    __shared__ int cnt[NCAM], offs[NCAM];
    int tid = threadIdx.x;
    if (tid < NCAM) cnt[tid] = 0;
    __syncthreads();
    int c = cam[tid];
    atomicAdd(&cnt[c], 1);
    __syncthreads();
    if (tid == 0){
        int s = 0;
        for (int i = 0; i < NCAM; i++){ offs[i] = s; g_seg[i] = s; s += cnt[i]; }
        g_seg[NCAM] = s;
        int nm = 0;
        // pairs first (2-tile cameras), aligned to even indices
        for (int i = 0; i < NCAM; i++){
            if (cnt[i] > TM && nm + 1 < MAXMT){
                g_mtile[nm++] = (i << 1) | 0;
                g_mtile[nm++] = (i << 1) | 1;
            }
        }
        // singletons
        for (int i = 0; i < NCAM; i++){
            if (cnt[i] > 0 && cnt[i] <= TM && nm < MAXMT)
                g_mtile[nm++] = (i << 1) | 0;
        }
        g_nmt = nm;
        for (int k = nm; k < MAXMT; k++) g_mtile[k] = -1;
    }
    __syncthreads();
    int p = atomicAdd(&offs[c], 1);
    g_order[p] = tid;
}

// ---------------- init: pack x (sorted+swizzled), zero hP/hA ----------------
#define XCH   (NCAM*2*NK*256)
#define HPCH  (NCAM*2*NK*256)
__global__ void init_pack_kernel(const float* __restrict__ x){
    const int total = XCH + 2*HPCH + BATCH*H/4;
    int stride = gridDim.x*blockDim.x;
    for (int i = blockIdx.x*blockDim.x + threadIdx.x; i < total; i += stride){
        if (i < XCH){
            int blk = i >> 8, cin = i & 255;
            int r = cin >> 3, ch = cin & 7;
            int kt = blk & 15, cm = blk >> 4;
            int mt = cm & 1, c = cm >> 1;
            int seg0 = g_seg[c], bc = g_seg[c+1]-seg0;
            int mg = mt*TM + r;
            uint4 v = make_uint4(0,0,0,0);
            if (mg < bc){
                int bidx = g_order[seg0+mg];
                const float4* s = (const float4*)(x + (size_t)bidx*H + kt*KC + ch*8);
                float4 a = s[0], b = s[1];
                __half2 h0 = __floats2half2_rn(a.x,a.y), h1 = __floats2half2_rn(a.z,a.w);
                __half2 h2 = __floats2half2_rn(b.x,b.y), h3 = __floats2half2_rn(b.z,b.w);
                v.x = *(uint32_t*)&h0; v.y = *(uint32_t*)&h1;
                v.z = *(uint32_t*)&h2; v.w = *(uint32_t*)&h3;
            }
            *(uint4*)(g_xpack + (size_t)blk*A_STG + r*128 + ((ch ^ (r&7))<<4)) = v;
        } else if (i < XCH + 2*HPCH){
            int k = i - XCH;
            if (k < HPCH) ((uint4*)g_hPA)[k] = make_uint4(0,0,0,0);
            else          ((uint4*)g_hPB)[k-HPCH] = make_uint4(0,0,0,0);
        } else {
            int k = i - XCH - 2*HPCH;
            ((float4*)g_hA)[k] = make_float4(0.f,0.f,0.f,0.f);
        }
    }
}

// ---------------- convert + pack weights fp32 -> fp16 swizzled tiles ----------------
__global__ void convert_pack_kernel(const float* __restrict__ wi, const float* __restrict__ wh){
    const size_t NCH = (size_t)NCAM*32*NK*768;
    size_t stride = (size_t)gridDim.x*blockDim.x;
    for (size_t i = (size_t)blockIdx.x*blockDim.x + threadIdx.x; i < NCH; i += stride){
        size_t blk = i / 768; int cin = (int)(i % 768);
        int r = cin >> 3, ch = cin & 7;
        int kt = (int)(blk & 15); size_t cj = blk >> 4;
        int jt = (int)(cj & 31); int c = (int)(cj >> 5);
        int grow = ((r>>5)<<10) + jt*TJ + (r & 31);
        size_t src = (((size_t)c*G3H + grow)<<10) + kt*KC + ch*8;
        size_t dst = blk*B_STG + r*128 + ((ch ^ (r&7))<<4);
        {
            const float4* s = (const float4*)(wi + src);
            float4 a = __ldcs(s), b = __ldcs(s+1);
            __half2 h0 = __floats2half2_rn(a.x,a.y), h1 = __floats2half2_rn(a.z,a.w);
            __half2 h2 = __floats2half2_rn(b.x,b.y), h3 = __floats2half2_rn(b.z,b.w);
            uint4 v; v.x=*(uint32_t*)&h0; v.y=*(uint32_t*)&h1; v.z=*(uint32_t*)&h2; v.w=*(uint32_t*)&h3;
            __stcs((uint4*)(g_Pwih + dst), v);
        }
        {
            const float4* s = (const float4*)(wh + src);
            float4 a = __ldcs(s), b = __ldcs(s+1);
            __half2 h0 = __floats2half2_rn(a.x,a.y), h1 = __floats2half2_rn(a.z,a.w);
            __half2 h2 = __floats2half2_rn(b.x,b.y), h3 = __floats2half2_rn(b.z,b.w);
            uint4 v; v.x=*(uint32_t*)&h0; v.y=*(uint32_t*)&h1; v.z=*(uint32_t*)&h2; v.w=*(uint32_t*)&h3;
            *(uint4*)(g_Pwhh + dst) = v;
        }
    }
}

// ---------------- clustered bulk-fed GEMM + fused GRU epilogue ----------------
template<int MODE>
__global__ void __launch_bounds__(256, 4) __cluster_dims__(1, 2, 1)
gemm_step_kernel(const float* __restrict__ b_ih, const float* __restrict__ b_hh, int t)
{
    extern __shared__ __align__(128) char smem[];
    const int jt = blockIdx.x;
    const int y  = blockIdx.y;
    const int rank = y & 1;
    const int cm  = g_mtile[y];
    const int cmp = g_mtile[y ^ 1];
    const bool active = (cm >= 0);
    const bool paired = active && (cmp >= 0) && ((cm >> 1) == (cmp >> 1));

    const int tid  = threadIdx.x;
    uint32_t smem_u32 = (uint32_t)__cvta_generic_to_shared(smem);
    uint32_t mbF = smem_u32 + SMEM_MAIN;       // 3 full barriers
    uint32_t mbE = mbF + 24;                   // 3 empty barriers

    if (tid == 0){
        uint32_t ecnt = paired ? 2u : 1u;
        #pragma unroll
        for (int s = 0; s < NSTG; s++){ mbar_init(mbF + s*8, 1); mbar_init(mbE + s*8, ecnt); }
        asm volatile("fence.proxy.async.shared::cta;" ::: "memory");
    }
    __syncthreads();
    CLUSTER_SYNC();        // all barriers visible cluster-wide before multicast

    if (active){
        const int c  = cm >> 1;
        const int mt = cm & 1;
        const int seg0 = g_seg[c];
        const int bc   = g_seg[c+1] - seg0;

        const char* __restrict__ Apack = (MODE==0) ? g_xpack : ((t & 1) ? g_hPB : g_hPA);
        const char* __restrict__ Bpack = (MODE==0) ? g_Pwih : g_Pwhh;
        const char* Asrc = Apack + (size_t)((c*2+mt)*NK)*A_STG;
        const char* Bsrc = Bpack + (size_t)((c*32+jt)*NK)*B_STG;

        const int j0   = jt*TJ;
        const int lane = tid & 31, warp = tid >> 5;
        const int wm = warp & 1, wn = warp >> 1;

        auto issue = [&](int kt){
            if (kt < NK){
                int s = kt % NSTG, q = kt / NSTG;
                if (q >= 1) mbar_wait(mbE + s*8, (q-1) & 1);
                uint32_t stg = smem_u32 + s*STAGE_BYTES;
                mbar_expect(mbF + s*8, STAGE_BYTES);
                bulk_g2s(stg, Asrc + (size_t)kt*A_STG, A_STG, mbF + s*8);
                if (paired){
                    // cooperative slicing: each rank loads its half, multicast to both
                    bulk_g2s_mc(stg + A_STG + rank*B_HALF,
                                Bsrc + (size_t)kt*B_STG + rank*B_HALF,
                                B_HALF, mbF + s*8, 0x3);
                } else {
                    bulk_g2s(stg + A_STG, Bsrc + (size_t)kt*B_STG, B_STG, mbF + s*8);
                }
            }
        };
        if (tid == 0){ issue(0); issue(1); issue(2); }

        float acc[3][4];
        #pragma unroll
        for (int i = 0; i < 3; i++)
            #pragma unroll
            for (int j = 0; j < 4; j++) acc[i][j] = 0.f;

        const int rowA = wm*16 + (lane & 7) + (lane & 8);
        const int cbA  = lane >> 4;
        const int rowBl = lane & 7;
        const int cbB  = (lane >> 3) & 1;

        for (int kt = 0; kt < NK; kt++){
            int s = kt % NSTG;
            mbar_wait(mbF + s*8, (kt/NSTG) & 1);
            uint32_t sA = smem_u32 + s*STAGE_BYTES;
            uint32_t sB = sA + A_STG;
            #pragma unroll
            for (int k16 = 0; k16 < KC/16; k16++){
                int cb = k16*2;
                uint32_t aaddr = sA + rowA*128 + (((cb + cbA) ^ (rowA & 7)) << 4);
                uint32_t a0,a1,a2,a3;
                asm volatile("ldmatrix.sync.aligned.m8n8.x4.shared.b16 {%0,%1,%2,%3}, [%4];"
                             : "=r"(a0),"=r"(a1),"=r"(a2),"=r"(a3) : "r"(aaddr));
                #pragma unroll
                for (int nt = 0; nt < 3; nt++){
                    int rB = wn*24 + nt*8 + rowBl;
                    uint32_t baddr = sB + rB*128 + (((cb + cbB) ^ (rB & 7)) << 4);
                    uint32_t b0,b1;
                    asm volatile("ldmatrix.sync.aligned.m8n8.x2.shared.b16 {%0,%1}, [%2];"
                                 : "=r"(b0),"=r"(b1) : "r"(baddr));
                    asm volatile("mma.sync.aligned.m16n8k16.row.col.f32.f16.f16.f32 "
                                 "{%0,%1,%2,%3}, {%4,%5,%6,%7}, {%8,%9}, {%0,%1,%2,%3};"
                                 : "+f"(acc[nt][0]),"+f"(acc[nt][1]),"+f"(acc[nt][2]),"+f"(acc[nt][3])
                                 : "r"(a0),"r"(a1),"r"(a2),"r"(a3),"r"(b0),"r"(b1));
                }
            }
            __syncthreads();
            if (tid == 0){
                mbar_arrive(mbE + s*8);                       // I'm done with stage s
                if (paired) mbar_arrive_peer(mbE + s*8, rank ^ 1);
                issue(kt + NSTG);
            }
        }

        // stash gh tile (stride 104 floats), fused epilogue
        float* ghs = (float*)smem;
        {
            int r0 = wm*16 + (lane >> 2);
            int colb = (lane & 3)*2;
            #pragma unroll
            for (int nt = 0; nt < 3; nt++){
                int ccol = wn*24 + nt*8 + colb;
                ghs[r0*104 + ccol]         = acc[nt][0];
                ghs[r0*104 + ccol + 1]     = acc[nt][1];
                ghs[(r0+8)*104 + ccol]     = acc[nt][2];
                ghs[(r0+8)*104 + ccol + 1] = acc[nt][3];
            }
        }
        __syncthreads();

        if (MODE == 0){
            for (int idx = tid; idx < TM*TN/4; idx += 256){
                int m = idx / 24, q = idx % 24;
                int nl = q*4;
                int mg = mt*TM + m;
                if (mg < bc){
                    int bidx = g_order[seg0 + mg];
                    int g = nl >> 5, jj = nl & 31;
                    int wrow = (g<<10) + j0 + jj;
                    float4 v = *(float4*)&ghs[m*104 + nl];
                    float4 bi = __ldg((const float4*)(b_ih + (size_t)c*G3H + wrow));
                    v.x += bi.x; v.y += bi.y; v.z += bi.z; v.w += bi.w;
                    if (g < 2){
                        float4 bh = __ldg((const float4*)(b_hh + (size_t)c*G3H + wrow));
                        v.x += bh.x; v.y += bh.y; v.z += bh.z; v.w += bh.w;
                    }
                    *(float4*)(g_gi + (size_t)bidx*G3H + wrow) = v;
                }
            }
        } else {
            const float* __restrict__ hc = (t & 1) ? g_hB : g_hA;
            float*       __restrict__ hn = (t & 1) ? g_hA : g_hB;
            char*        __restrict__ hPn = (t & 1) ? g_hPA : g_hPB;
            int m = tid >> 3, jj = (tid & 7)*4;
            int mg = mt*TM + m;
            if (mg < bc){
                int bidx = g_order[seg0 + mg];
                int j = j0 + jj;
                float4 ghr = *(float4*)&ghs[m*104 + jj];
                float4 ghz = *(float4*)&ghs[m*104 + 32 + jj];
                float4 ghn4 = *(float4*)&ghs[m*104 + 64 + jj];
                const float* gi = g_gi + (size_t)bidx*G3H;
                float4 gir = *(const float4*)(gi + j);
                float4 giz = *(const float4*)(gi + H + j);
                float4 gin = *(const float4*)(gi + 2*H + j);
                float4 bn  = __ldg((const float4*)(b_hh + (size_t)c*G3H + 2*H + j));
                float4 hold = *(const float4*)(hc + (size_t)bidx*H + j);
                float4 hv;
                {
                    float r0 = sigf(gir.x + ghr.x), z0 = sigf(giz.x + ghz.x);
                    float n0 = tanhfast(gin.x + r0*(ghn4.x + bn.x));
                    hv.x = (1.f - z0)*n0 + z0*hold.x;
                    float r1 = sigf(gir.y + ghr.y), z1 = sigf(giz.y + ghz.y);
                    float n1 = tanhfast(gin.y + r1*(ghn4.y + bn.y));
                    hv.y = (1.f - z1)*n1 + z1*hold.y;
                    float r2 = sigf(gir.z + ghr.z), z2 = sigf(giz.z + ghz.z);
                    float n2 = tanhfast(gin.z + r2*(ghn4.z + bn.z));
                    hv.z = (1.f - z2)*n2 + z2*hold.z;
                    float r3 = sigf(gir.w + ghr.w), z3 = sigf(giz.w + ghz.w);
                    float n3 = tanhfast(gin.w + r3*(ghn4.w + bn.w));
                    hv.w = (1.f - z3)*n3 + z3*hold.w;
                }
                *(float4*)(hn + (size_t)bidx*H + j) = hv;
                __stcs((float4*)(g_hs + ((size_t)t*BATCH + bidx)*H + j), hv);
                int kt = j >> 6, ch = (j >> 3) & 7, win = (j & 7)*2;
                __half2 p0 = __floats2half2_rn(hv.x, hv.y);
                __half2 p1 = __floats2half2_rn(hv.z, hv.w);
                uint2 pk; pk.x = *(uint32_t*)&p0; pk.y = *(uint32_t*)&p1;
                *(uint2*)(hPn + (size_t)((c*2+mt)*NK + kt)*A_STG + m*128 + ((ch ^ (m&7))<<4) + win) = pk;
            }
        }
    }

    // no CTA may exit while peer ops may target its SMEM
    CLUSTER_SYNC();
}

// ---------------- final transpose [T,B,H] -> [B,H,T] ----------------
__global__ void transpose_kernel(float* __restrict__ out){
    __shared__ float tile[NT*65];
    int b = blockIdx.y, j0 = blockIdx.x*64, tid = threadIdx.x;
    for (int idx = tid; idx < NT*64; idx += 256){
        int t = idx >> 6, jj = idx & 63;
        tile[t*65 + jj] = __ldcs(&g_hs[((size_t)t*BATCH + b)*H + j0 + jj]);
    }
    __syncthreads();
    for (int idx = tid; idx < NT*64; idx += 256){
        int jj = idx / NT, t = idx % NT;
        __stcs(&out[((size_t)b*H + j0 + jj)*NT + t], tile[t*65 + jj]);
    }
}

// ---------------- launch ----------------
extern "C" void kernel_launch(void* const* d_in, const int* in_sizes, int n_in,
                              void* d_out, int out_size)
{
    const float* x   = (const float*)d_in[0];
    const int*   cam = (const int*)  d_in[1];
    const float* Wih = (const float*)d_in[2];
    const float* Whh = (const float*)d_in[3];
    const float* bih = (const float*)d_in[4];
    const float* bhh = (const float*)d_in[5];
    float* out = (float*)d_out;

    cudaFuncSetAttribute(gemm_step_kernel<0>, cudaFuncAttributeMaxDynamicSharedMemorySize, SMEM_DYN);
    cudaFuncSetAttribute(gemm_step_kernel<1>, cudaFuncAttributeMaxDynamicSharedMemorySize, SMEM_DYN);

    setup_kernel<<<1, 256>>>(cam);
    init_pack_kernel<<<512, 256>>>(x);
    convert_pack_kernel<<<4096, 256>>>(Wih, Whh);

    dim3 grid(32, MAXMT);
    gemm_step_kernel<0><<<grid, 256, SMEM_DYN>>>(bih, bhh, -1);
    for (int t = 0; t < NT; t++)
        gemm_step_kernel<1><<<grid, 256, SMEM_DYN>>>(bih, bhh, t);

    transpose_kernel<<<dim3(16, BATCH), 256>>>(out);
}